// round 2
// baseline (speedup 1.0000x reference)
#include <cuda_runtime.h>
#include <math_constants.h>
#include <cstdint>

#define NB 2
#define NPTS 8192
#define NBINS 4096
#define NORM_MAX 8.0f
#define BINWIDTH (NORM_MAX / (float)NBINS)
#define SLACK (BINWIDTH + 1e-3f)
#define FULLM 0xffffffffu

// Static scratch (no allocations allowed)
__device__ float4 g_tmpP[NB * NPTS];      // p = xyz1+flow1, w=|p|^2 (unsorted, by orig idx)
__device__ float4 g_sorted[NB * NPTS];    // candidates sorted ascending by |p| (bin-granular)
__device__ int    g_sortedIdx[NB * NPTS]; // sorted pos -> original index
__device__ int    g_qorder[NB * NPTS];    // queries sorted ascending by |q|
__device__ int    g_histC[NB * NBINS];
__device__ int    g_histQ[NB * NBINS];

__device__ __forceinline__ int norm_bin(float n) {
    int b = (int)(n * ((float)NBINS / NORM_MAX));
    return b < NBINS - 1 ? b : NBINS - 1;
}

__global__ void k0_zero() {
    int i = blockIdx.x * blockDim.x + threadIdx.x;
    if (i < NB * NBINS) { g_histC[i] = 0; g_histQ[i] = 0; }
}

__global__ void k1_prep(const float* __restrict__ xyz1,
                        const float* __restrict__ xyz2,
                        const float* __restrict__ flow1) {
    int idx = blockIdx.x * blockDim.x + threadIdx.x;
    if (idx >= NB * NPTS) return;
    int b = idx / NPTS, i = idx - b * NPTS;
    const float* X1 = xyz1 + b * 3 * NPTS;
    const float* F  = flow1 + b * 3 * NPTS;
    float px = X1[i]            + F[i];
    float py = X1[NPTS + i]     + F[NPTS + i];
    float pz = X1[2 * NPTS + i] + F[2 * NPTS + i];
    float pw = fmaf(px, px, fmaf(py, py, pz * pz));
    g_tmpP[idx] = make_float4(px, py, pz, pw);
    atomicAdd(&g_histC[b * NBINS + norm_bin(sqrtf(pw))], 1);

    const float* X2 = xyz2 + b * 3 * NPTS;
    float qx = X2[i], qy = X2[NPTS + i], qz = X2[2 * NPTS + i];
    float qn = sqrtf(fmaf(qx, qx, fmaf(qy, qy, qz * qz)));
    atomicAdd(&g_histQ[b * NBINS + norm_bin(qn)], 1);
}

// 4 blocks: 0..1 -> histC per batch, 2..3 -> histQ per batch. 1024 threads, 4 bins each.
__global__ void k2_scan() {
    int which = blockIdx.x;
    int* H = (which < NB) ? (g_histC + which * NBINS)
                          : (g_histQ + (which - NB) * NBINS);
    __shared__ int sh[1024];
    int t = threadIdx.x;
    int a0 = H[4*t], a1 = H[4*t+1], a2 = H[4*t+2], a3 = H[4*t+3];
    int s = a0 + a1 + a2 + a3;
    sh[t] = s;
    __syncthreads();
    for (int off = 1; off < 1024; off <<= 1) {
        int v = (t >= off) ? sh[t - off] : 0;
        __syncthreads();
        sh[t] += v;
        __syncthreads();
    }
    int excl = sh[t] - s;
    H[4*t]   = excl;
    H[4*t+1] = excl + a0;
    H[4*t+2] = excl + a0 + a1;
    H[4*t+3] = excl + a0 + a1 + a2;
}

__global__ void k3_scatter(const float* __restrict__ xyz2) {
    int idx = blockIdx.x * blockDim.x + threadIdx.x;
    if (idx >= NB * NPTS) return;
    int b = idx / NPTS, i = idx - b * NPTS;

    float4 p = g_tmpP[idx];
    int bin = norm_bin(sqrtf(p.w));
    int pos = atomicAdd(&g_histC[b * NBINS + bin], 1);
    g_sorted[b * NPTS + pos] = p;
    g_sortedIdx[b * NPTS + pos] = i;

    const float* X2 = xyz2 + b * 3 * NPTS;
    float qx = X2[i], qy = X2[NPTS + i], qz = X2[2 * NPTS + i];
    float qn = sqrtf(fmaf(qx, qx, fmaf(qy, qy, qz * qz)));
    int qpos = atomicAdd(&g_histQ[b * NBINS + norm_bin(qn)], 1);
    g_qorder[b * NPTS + qpos] = i;
}

// One warp per 32 norm-adjacent queries; expanding window over norm-sorted candidates.
__global__ void __launch_bounds__(32)
k4_knn(const float* __restrict__ xyz2,
       const float* __restrict__ flow1,
       float* __restrict__ out) {
    const int lane = threadIdx.x;
    const int w = blockIdx.x;                 // 0 .. NB*NPTS/32-1
    const int b = w / (NPTS / 32);
    const int g = w % (NPTS / 32);
    const int bN = b * NPTS;

    const int qi = g_qorder[bN + g * 32 + lane];
    const float* X2 = xyz2 + b * 3 * NPTS;
    const float qx = X2[qi], qy = X2[NPTS + qi], qz = X2[2 * NPTS + qi];
    const float qn2 = fmaf(qx, qx, fmaf(qy, qy, qz * qz));
    const float qn  = sqrtf(qn2);
    const float m2x = -2.f * qx, m2y = -2.f * qy, m2z = -2.f * qz;
    const float cn = __shfl_sync(FULLM, qn, 16);   // warp-uniform group center norm

    float bs0 = CUDART_INF_F, bs1 = CUDART_INF_F, bs2 = CUDART_INF_F;
    int   bp0 = 0, bp1 = 0, bp2 = 0;

    const float4* src = g_sorted + bN;
    int lo = g_histC[b * NBINS + norm_bin(cn)];    // end-offset of center bin
    if (lo > NPTS) lo = NPTS;
    int hi = lo;

    for (int step = 0; step < 640; step++) {
        float nl = (lo > 0)    ? sqrtf(src[lo - 1].w) : 0.0f;
        float nr = (hi < NPTS) ? sqrtf(src[hi].w)     : 0.0f;
        float d3sq = bs2 + qn2;

        bool doneL = (lo == 0), doneR = (hi == NPTS);
        if (!doneL) { float gl = qn - nl - SLACK; doneL = (gl > 0.f) && (gl * gl > d3sq); }
        if (!doneR) { float gr = nr - qn - SLACK; doneR = (gr > 0.f) && (gr * gr > d3sq); }

        unsigned mL = __ballot_sync(FULLM, doneL);
        unsigned mR = __ballot_sync(FULLM, doneR);
        if ((mL & mR) == FULLM) break;

        bool pickL;
        if (mL == FULLM)      pickL = false;   // hi < NPTS guaranteed
        else if (mR == FULLM) pickL = true;    // lo > 0 guaranteed
        else                  pickL = (cn - nl) <= (nr - cn);

        if (pickL) {
            int base = lo - 32; if (base < 0) base = 0;
            int cnt = lo - base;
#pragma unroll 4
            for (int c = 0; c < cnt; c++) {
                int pos = base + c;
                float4 p = src[pos];
                float s = fmaf(p.x, m2x, fmaf(p.y, m2y, fmaf(p.z, m2z, p.w)));
                if (s < bs2) {
                    if (s < bs1) {
                        bs2 = bs1; bp2 = bp1;
                        if (s < bs0) { bs1 = bs0; bp1 = bp0; bs0 = s; bp0 = pos; }
                        else         { bs1 = s;   bp1 = pos; }
                    } else { bs2 = s; bp2 = pos; }
                }
            }
            lo = base;
        } else {
            int cnt = NPTS - hi; if (cnt > 32) cnt = 32;
            int base = hi;
#pragma unroll 4
            for (int c = 0; c < cnt; c++) {
                int pos = base + c;
                float4 p = src[pos];
                float s = fmaf(p.x, m2x, fmaf(p.y, m2y, fmaf(p.z, m2z, p.w)));
                if (s < bs2) {
                    if (s < bs1) {
                        bs2 = bs1; bp2 = bp1;
                        if (s < bs0) { bs1 = bs0; bp1 = bp0; bs0 = s; bp0 = pos; }
                        else         { bs1 = s;   bp1 = pos; }
                    } else { bs2 = s; bp2 = pos; }
                }
            }
            hi = base + cnt;
        }
    }

    // Finalize: exact distances -> inverse-distance weights -> gather flow -> warp
    int pp[3] = { bp0, bp1, bp2 };
    float wk[3];
    float wsum = 0.f;
#pragma unroll
    for (int k = 0; k < 3; k++) {
        float4 p = src[pp[k]];
        float dx = p.x - qx, dy = p.y - qy, dz = p.z - qz;
        float d = sqrtf(fmaf(dx, dx, fmaf(dy, dy, dz * dz)));
        d = fmaxf(d, 1e-10f);
        float inv = 1.0f / d;
        wk[k] = inv;
        wsum += inv;
    }
    const float rs = 1.0f / wsum;

    const float* F = flow1 + b * 3 * NPTS;
    float fx = 0.f, fy = 0.f, fz = 0.f;
#pragma unroll
    for (int k = 0; k < 3; k++) {
        int o = g_sortedIdx[bN + pp[k]];
        float ww = wk[k] * rs;
        fx = fmaf(ww, F[o],            fx);
        fy = fmaf(ww, F[NPTS + o],     fy);
        fz = fmaf(ww, F[2 * NPTS + o], fz);
    }

    float* O = out + b * 3 * NPTS;
    O[qi]            = qx - fx;
    O[NPTS + qi]     = qy - fy;
    O[2 * NPTS + qi] = qz - fz;
}

extern "C" void kernel_launch(void* const* d_in, const int* in_sizes, int n_in,
                              void* d_out, int out_size) {
    const float* xyz1  = (const float*)d_in[0];
    const float* xyz2  = (const float*)d_in[1];
    const float* flow1 = (const float*)d_in[2];
    float* out = (float*)d_out;

    k0_zero<<<(NB * NBINS + 255) / 256, 256>>>();
    k1_prep<<<(NB * NPTS + 255) / 256, 256>>>(xyz1, xyz2, flow1);
    k2_scan<<<NB * 2, 1024>>>();
    k3_scatter<<<(NB * NPTS + 255) / 256, 256>>>(xyz2);
    k4_knn<<<NB * NPTS / 32, 32>>>(xyz2, flow1, out);
}

// round 3
// speedup vs baseline: 1.8002x; 1.8002x over previous
#include <cuda_runtime.h>
#include <math_constants.h>
#include <cstdint>

#define NB 2
#define NPTS 8192
#define NQ (NB * NPTS)
#define SLICES 4
#define SLICE_CAND (NPTS / SLICES)     // 2048
#define SLICE_PAIRS (SLICE_CAND / 2)   // 1024
#define QPB 256                        // queries per k4 block
#define K4_THREADS 128
#define INF CUDART_INF_F

// Candidate pair layout: pair j -> g_pairs[2j]=(x0,x1,y0,y1), g_pairs[2j+1]=(z0,z1,w0,w1)
__device__ float4 g_pairs[NB * (NPTS / 2) * 2];
__device__ float4 g_pts[NB * NPTS];                // (x,y,z,|p|^2) by original index
__device__ float  g_pScore[NQ * SLICES * 3];
__device__ int    g_pIdx[NQ * SLICES * 3];

__device__ __forceinline__ uint64_t dup2(float v) {
    uint64_t r; asm("mov.b64 %0,{%1,%1};" : "=l"(r) : "f"(v)); return r;
}
__device__ __forceinline__ uint64_t fma2(uint64_t a, uint64_t b, uint64_t c) {
    uint64_t d; asm("fma.rn.f32x2 %0,%1,%2,%3;" : "=l"(d) : "l"(a), "l"(b), "l"(c)); return d;
}
__device__ __forceinline__ void unpack2(uint64_t v, float& lo, float& hi) {
    asm("mov.b64 {%0,%1},%2;" : "=f"(lo), "=f"(hi) : "l"(v));
}

#define INS3(bs0, bs1, bs2, bi0, bi1, bi2, s, id)            \
    if ((s) < (bs2)) {                                       \
        if ((s) < (bs1)) {                                   \
            bs2 = bs1; bi2 = bi1;                            \
            if ((s) < (bs0)) { bs1 = bs0; bi1 = bi0;         \
                               bs0 = (s); bi0 = (id); }      \
            else             { bs1 = (s); bi1 = (id); }      \
        } else { bs2 = (s); bi2 = (id); }                    \
    }

__global__ void k1_prep(const float* __restrict__ xyz1,
                        const float* __restrict__ flow1) {
    int t = blockIdx.x * blockDim.x + threadIdx.x;
    if (t >= NB * (NPTS / 2)) return;
    int b = t / (NPTS / 2), j = t % (NPTS / 2);
    const float* X = xyz1 + b * 3 * NPTS;
    const float* F = flow1 + b * 3 * NPTS;
    int c = 2 * j;
    float x0 = X[c] + F[c],                         x1 = X[c + 1] + F[c + 1];
    float y0 = X[NPTS + c] + F[NPTS + c],           y1 = X[NPTS + c + 1] + F[NPTS + c + 1];
    float z0 = X[2 * NPTS + c] + F[2 * NPTS + c],   z1 = X[2 * NPTS + c + 1] + F[2 * NPTS + c + 1];
    float w0 = fmaf(x0, x0, fmaf(y0, y0, z0 * z0));
    float w1 = fmaf(x1, x1, fmaf(y1, y1, z1 * z1));
    g_pairs[(b * (NPTS / 2) + j) * 2 + 0] = make_float4(x0, x1, y0, y1);
    g_pairs[(b * (NPTS / 2) + j) * 2 + 1] = make_float4(z0, z1, w0, w1);
    g_pts[b * NPTS + c]     = make_float4(x0, y0, z0, w0);
    g_pts[b * NPTS + c + 1] = make_float4(x1, y1, z1, w1);
}

// 256 queries/block vs one candidate slice; 2 queries per lane; f32x2 scores.
__global__ void __launch_bounds__(K4_THREADS)
k4_scan(const float* __restrict__ xyz2) {
    __shared__ float4 sh[SLICE_PAIRS * 2];   // 32 KB

    const int blk   = blockIdx.x;
    const int slice = blk & (SLICES - 1);
    const int qg    = blk >> 2;              // 0..63
    const int batch = qg >> 5;               // NPTS/QPB = 32 qgroups per batch
    const int qbase = (qg & 31) * QPB;
    const int lane  = threadIdx.x & 31;
    const int w     = threadIdx.x >> 5;

    // Stage slice into shared (contiguous, coalesced)
    const float4* src = g_pairs + (size_t)(batch * (NPTS / 2) + slice * SLICE_PAIRS) * 2;
#pragma unroll
    for (int i = threadIdx.x; i < SLICE_PAIRS * 2; i += K4_THREADS)
        sh[i] = src[i];
    __syncthreads();

    const int qA = qbase + w * 64 + lane;    // within batch
    const int qB = qA + 32;
    const float* X2 = xyz2 + batch * 3 * NPTS;
    const float aX = X2[qA], aY = X2[NPTS + qA], aZ = X2[2 * NPTS + qA];
    const float bX = X2[qB], bY = X2[NPTS + qB], bZ = X2[2 * NPTS + qB];

    const uint64_t Amx = dup2(-2.f * aX), Amy = dup2(-2.f * aY), Amz = dup2(-2.f * aZ);
    const uint64_t Bmx = dup2(-2.f * bX), Bmy = dup2(-2.f * bY), Bmz = dup2(-2.f * bZ);

    float As0 = INF, As1 = INF, As2 = INF;  int Ai0 = 0, Ai1 = 0, Ai2 = 0;
    float Bs0 = INF, Bs1 = INF, Bs2 = INF;  int Bi0 = 0, Bi1 = 0, Bi2 = 0;

    const uint32_t shbase = (uint32_t)__cvta_generic_to_shared(sh);
    const int cbase = slice * SLICE_CAND;    // global (within-batch) candidate base

#pragma unroll 4
    for (int j = 0; j < SLICE_PAIRS; j++) {
        uint64_t xp, yp, zp, wp;
        const uint32_t addr = shbase + j * 32;
        asm("ld.shared.v2.u64 {%0,%1},[%2];"    : "=l"(xp), "=l"(yp) : "r"(addr));
        asm("ld.shared.v2.u64 {%0,%1},[%2+16];" : "=l"(zp), "=l"(wp) : "r"(addr));

        uint64_t sA = fma2(xp, Amx, fma2(yp, Amy, fma2(zp, Amz, wp)));
        uint64_t sB = fma2(xp, Bmx, fma2(yp, Bmy, fma2(zp, Bmz, wp)));
        float a0, a1, b0, b1;
        unpack2(sA, a0, a1);
        unpack2(sB, b0, b1);

        if (fminf(a0, a1) < As2) {
            const int id = cbase + 2 * j;
            INS3(As0, As1, As2, Ai0, Ai1, Ai2, a0, id);
            INS3(As0, As1, As2, Ai0, Ai1, Ai2, a1, id + 1);
        }
        if (fminf(b0, b1) < Bs2) {
            const int id = cbase + 2 * j;
            INS3(Bs0, Bs1, Bs2, Bi0, Bi1, Bi2, b0, id);
            INS3(Bs0, Bs1, Bs2, Bi0, Bi1, Bi2, b1, id + 1);
        }
    }

    // Write partials: layout [query][slice][3]
    const int gqA = batch * NPTS + qA;
    const int gqB = batch * NPTS + qB;
    int offA = (gqA * SLICES + slice) * 3;
    int offB = (gqB * SLICES + slice) * 3;
    g_pScore[offA] = As0; g_pScore[offA + 1] = As1; g_pScore[offA + 2] = As2;
    g_pIdx[offA]   = Ai0; g_pIdx[offA + 1]   = Ai1; g_pIdx[offA + 2]   = Ai2;
    g_pScore[offB] = Bs0; g_pScore[offB + 1] = Bs1; g_pScore[offB + 2] = Bs2;
    g_pIdx[offB]   = Bi0; g_pIdx[offB + 1]   = Bi1; g_pIdx[offB + 2]   = Bi2;
}

// Merge 4 slice-partials per query (ascending slice order + strict < keeps
// top_k's lowest-index tie-break), then epilogue.
__global__ void k5_final(const float* __restrict__ xyz2,
                         const float* __restrict__ flow1,
                         float* __restrict__ out) {
    int q = blockIdx.x * blockDim.x + threadIdx.x;
    if (q >= NQ) return;
    const int b = q / NPTS, n = q % NPTS;

    float bs0 = INF, bs1 = INF, bs2 = INF;
    int   bi0 = 0,   bi1 = 0,   bi2 = 0;
    const int off = q * SLICES * 3;
#pragma unroll
    for (int k = 0; k < SLICES * 3; k++) {
        float s = g_pScore[off + k];
        int  id = g_pIdx[off + k];
        INS3(bs0, bs1, bs2, bi0, bi1, bi2, s, id);
    }

    const float* X2 = xyz2 + b * 3 * NPTS;
    const float qx = X2[n], qy = X2[NPTS + n], qz = X2[2 * NPTS + n];

    const float4* pts = g_pts + b * NPTS;
    int   pp[3] = { bi0, bi1, bi2 };
    float wk[3];
    float wsum = 0.f;
#pragma unroll
    for (int k = 0; k < 3; k++) {
        float4 p = pts[pp[k]];
        float dx = p.x - qx, dy = p.y - qy, dz = p.z - qz;
        float d = sqrtf(fmaf(dx, dx, fmaf(dy, dy, dz * dz)));
        d = fmaxf(d, 1e-10f);
        float inv = 1.0f / d;
        wk[k] = inv;
        wsum += inv;
    }
    const float rs = 1.0f / wsum;

    const float* F = flow1 + b * 3 * NPTS;
    float fx = 0.f, fy = 0.f, fz = 0.f;
#pragma unroll
    for (int k = 0; k < 3; k++) {
        int o = pp[k];
        float ww = wk[k] * rs;
        fx = fmaf(ww, F[o],            fx);
        fy = fmaf(ww, F[NPTS + o],     fy);
        fz = fmaf(ww, F[2 * NPTS + o], fz);
    }

    float* O = out + b * 3 * NPTS;
    O[n]            = qx - fx;
    O[NPTS + n]     = qy - fy;
    O[2 * NPTS + n] = qz - fz;
}

extern "C" void kernel_launch(void* const* d_in, const int* in_sizes, int n_in,
                              void* d_out, int out_size) {
    const float* xyz1  = (const float*)d_in[0];
    const float* xyz2  = (const float*)d_in[1];
    const float* flow1 = (const float*)d_in[2];
    float* out = (float*)d_out;

    k1_prep<<<(NB * (NPTS / 2) + 255) / 256, 256>>>(xyz1, flow1);
    k4_scan<<<(NQ / QPB) * SLICES, K4_THREADS>>>(xyz2);     // 256 blocks
    k5_final<<<(NQ + 255) / 256, 256>>>(xyz2, flow1, out);
}

// round 4
// speedup vs baseline: 2.5151x; 1.3971x over previous
#include <cuda_runtime.h>
#include <math_constants.h>
#include <cstdint>

#define NB 2
#define NPTS 8192
#define NQ (NB * NPTS)
#define SLICES 16
#define SLICE_CAND (NPTS / SLICES)     // 512
#define SLICE_PAIRS (SLICE_CAND / 2)   // 256
#define QPB 256                        // queries per k4 block
#define K4_THREADS 128
#define INF CUDART_INF_F

// Candidate pair layout: pair j -> g_pairs[2j]=(x0,x1,y0,y1), g_pairs[2j+1]=(z0,z1,w0,w1)
__device__ float4 g_pairs[NB * (NPTS / 2) * 2];
__device__ float4 g_pts[NB * NPTS];                // (x,y,z,|p|^2) by original index
// Partials, transposed for coalescing: [slice][k(0..2)][query]
__device__ float  g_pScore[SLICES * 3 * NQ];
__device__ int    g_pIdx[SLICES * 3 * NQ];

__device__ __forceinline__ uint64_t dup2(float v) {
    uint64_t r; asm("mov.b64 %0,{%1,%1};" : "=l"(r) : "f"(v)); return r;
}
__device__ __forceinline__ uint64_t fma2(uint64_t a, uint64_t b, uint64_t c) {
    uint64_t d; asm("fma.rn.f32x2 %0,%1,%2,%3;" : "=l"(d) : "l"(a), "l"(b), "l"(c)); return d;
}
__device__ __forceinline__ void unpack2(uint64_t v, float& lo, float& hi) {
    asm("mov.b64 {%0,%1},%2;" : "=f"(lo), "=f"(hi) : "l"(v));
}

#define INS3(bs0, bs1, bs2, bi0, bi1, bi2, s, id)            \
    if ((s) < (bs2)) {                                       \
        if ((s) < (bs1)) {                                   \
            bs2 = bs1; bi2 = bi1;                            \
            if ((s) < (bs0)) { bs1 = bs0; bi1 = bi0;         \
                               bs0 = (s); bi0 = (id); }      \
            else             { bs1 = (s); bi1 = (id); }      \
        } else { bs2 = (s); bi2 = (id); }                    \
    }

__global__ void k1_prep(const float* __restrict__ xyz1,
                        const float* __restrict__ flow1) {
    int t = blockIdx.x * blockDim.x + threadIdx.x;
    if (t >= NB * (NPTS / 2)) return;
    int b = t / (NPTS / 2), j = t % (NPTS / 2);
    const float* X = xyz1 + b * 3 * NPTS;
    const float* F = flow1 + b * 3 * NPTS;
    int c = 2 * j;
    float x0 = X[c] + F[c],                         x1 = X[c + 1] + F[c + 1];
    float y0 = X[NPTS + c] + F[NPTS + c],           y1 = X[NPTS + c + 1] + F[NPTS + c + 1];
    float z0 = X[2 * NPTS + c] + F[2 * NPTS + c],   z1 = X[2 * NPTS + c + 1] + F[2 * NPTS + c + 1];
    float w0 = fmaf(x0, x0, fmaf(y0, y0, z0 * z0));
    float w1 = fmaf(x1, x1, fmaf(y1, y1, z1 * z1));
    g_pairs[(b * (NPTS / 2) + j) * 2 + 0] = make_float4(x0, x1, y0, y1);
    g_pairs[(b * (NPTS / 2) + j) * 2 + 1] = make_float4(z0, z1, w0, w1);
    g_pts[b * NPTS + c]     = make_float4(x0, y0, z0, w0);
    g_pts[b * NPTS + c + 1] = make_float4(x1, y1, z1, w1);
}

// 256 queries/block vs one 512-candidate slice; 2 queries per lane; f32x2 scores;
// one guard branch per query per 4 candidates.
__global__ void __launch_bounds__(K4_THREADS)
k4_scan(const float* __restrict__ xyz2) {
    __shared__ float4 sh[SLICE_PAIRS * 2];   // 8 KB

    const int blk   = blockIdx.x;
    const int slice = blk & (SLICES - 1);
    const int qg    = blk >> 4;              // 0..63
    const int batch = qg >> 5;               // 32 qgroups per batch
    const int qbase = (qg & 31) * QPB;
    const int lane  = threadIdx.x & 31;
    const int w     = threadIdx.x >> 5;

    const float4* src = g_pairs + (size_t)(batch * (NPTS / 2) + slice * SLICE_PAIRS) * 2;
#pragma unroll
    for (int i = threadIdx.x; i < SLICE_PAIRS * 2; i += K4_THREADS)
        sh[i] = src[i];
    __syncthreads();

    const int qA = qbase + w * 64 + lane;    // within batch
    const int qB = qA + 32;
    const float* X2 = xyz2 + batch * 3 * NPTS;
    const float aX = X2[qA], aY = X2[NPTS + qA], aZ = X2[2 * NPTS + qA];
    const float bX = X2[qB], bY = X2[NPTS + qB], bZ = X2[2 * NPTS + qB];

    const uint64_t Amx = dup2(-2.f * aX), Amy = dup2(-2.f * aY), Amz = dup2(-2.f * aZ);
    const uint64_t Bmx = dup2(-2.f * bX), Bmy = dup2(-2.f * bY), Bmz = dup2(-2.f * bZ);

    float As0 = INF, As1 = INF, As2 = INF;  int Ai0 = 0, Ai1 = 0, Ai2 = 0;
    float Bs0 = INF, Bs1 = INF, Bs2 = INF;  int Bi0 = 0, Bi1 = 0, Bi2 = 0;

    const uint32_t shbase = (uint32_t)__cvta_generic_to_shared(sh);
    const int cbase = slice * SLICE_CAND;

#pragma unroll 4
    for (int j = 0; j < SLICE_PAIRS; j += 2) {
        uint64_t xp0, yp0, zp0, wp0, xp1, yp1, zp1, wp1;
        const uint32_t addr = shbase + j * 32;
        asm("ld.shared.v2.u64 {%0,%1},[%2];"    : "=l"(xp0), "=l"(yp0) : "r"(addr));
        asm("ld.shared.v2.u64 {%0,%1},[%2+16];" : "=l"(zp0), "=l"(wp0) : "r"(addr));
        asm("ld.shared.v2.u64 {%0,%1},[%2+32];" : "=l"(xp1), "=l"(yp1) : "r"(addr));
        asm("ld.shared.v2.u64 {%0,%1},[%2+48];" : "=l"(zp1), "=l"(wp1) : "r"(addr));

        float a0, a1, a2, a3, b0, b1, b2, b3;
        unpack2(fma2(xp0, Amx, fma2(yp0, Amy, fma2(zp0, Amz, wp0))), a0, a1);
        unpack2(fma2(xp1, Amx, fma2(yp1, Amy, fma2(zp1, Amz, wp1))), a2, a3);
        unpack2(fma2(xp0, Bmx, fma2(yp0, Bmy, fma2(zp0, Bmz, wp0))), b0, b1);
        unpack2(fma2(xp1, Bmx, fma2(yp1, Bmy, fma2(zp1, Bmz, wp1))), b2, b3);

        if (fminf(fminf(a0, a1), fminf(a2, a3)) < As2) {
            const int id = cbase + 2 * j;
            INS3(As0, As1, As2, Ai0, Ai1, Ai2, a0, id);
            INS3(As0, As1, As2, Ai0, Ai1, Ai2, a1, id + 1);
            INS3(As0, As1, As2, Ai0, Ai1, Ai2, a2, id + 2);
            INS3(As0, As1, As2, Ai0, Ai1, Ai2, a3, id + 3);
        }
        if (fminf(fminf(b0, b1), fminf(b2, b3)) < Bs2) {
            const int id = cbase + 2 * j;
            INS3(Bs0, Bs1, Bs2, Bi0, Bi1, Bi2, b0, id);
            INS3(Bs0, Bs1, Bs2, Bi0, Bi1, Bi2, b1, id + 1);
            INS3(Bs0, Bs1, Bs2, Bi0, Bi1, Bi2, b2, id + 2);
            INS3(Bs0, Bs1, Bs2, Bi0, Bi1, Bi2, b3, id + 3);
        }
    }

    // Coalesced partial writes: [slice][k][query]
    const int gqA = batch * NPTS + qA;
    const int gqB = batch * NPTS + qB;
    const int sb = slice * 3 * NQ;
    g_pScore[sb + 0 * NQ + gqA] = As0;  g_pIdx[sb + 0 * NQ + gqA] = Ai0;
    g_pScore[sb + 1 * NQ + gqA] = As1;  g_pIdx[sb + 1 * NQ + gqA] = Ai1;
    g_pScore[sb + 2 * NQ + gqA] = As2;  g_pIdx[sb + 2 * NQ + gqA] = Ai2;
    g_pScore[sb + 0 * NQ + gqB] = Bs0;  g_pIdx[sb + 0 * NQ + gqB] = Bi0;
    g_pScore[sb + 1 * NQ + gqB] = Bs1;  g_pIdx[sb + 1 * NQ + gqB] = Bi1;
    g_pScore[sb + 2 * NQ + gqB] = Bs2;  g_pIdx[sb + 2 * NQ + gqB] = Bi2;
}

// Merge slice partials per query (ascending slice order + strict < keeps
// top_k's lowest-index tie-break), then epilogue.
__global__ void k5_final(const float* __restrict__ xyz2,
                         const float* __restrict__ flow1,
                         float* __restrict__ out) {
    int q = blockIdx.x * blockDim.x + threadIdx.x;
    if (q >= NQ) return;
    const int b = q / NPTS, n = q % NPTS;

    float bs0 = INF, bs1 = INF, bs2 = INF;
    int   bi0 = 0,   bi1 = 0,   bi2 = 0;
#pragma unroll
    for (int sl = 0; sl < SLICES; sl++) {
#pragma unroll
        for (int k = 0; k < 3; k++) {
            float s = g_pScore[(sl * 3 + k) * NQ + q];
            int  id = g_pIdx[(sl * 3 + k) * NQ + q];
            INS3(bs0, bs1, bs2, bi0, bi1, bi2, s, id);
        }
    }

    const float* X2 = xyz2 + b * 3 * NPTS;
    const float qx = X2[n], qy = X2[NPTS + n], qz = X2[2 * NPTS + n];

    const float4* pts = g_pts + b * NPTS;
    int   pp[3] = { bi0, bi1, bi2 };
    float wk[3];
    float wsum = 0.f;
#pragma unroll
    for (int k = 0; k < 3; k++) {
        float4 p = pts[pp[k]];
        float dx = p.x - qx, dy = p.y - qy, dz = p.z - qz;
        float d = sqrtf(fmaf(dx, dx, fmaf(dy, dy, dz * dz)));
        d = fmaxf(d, 1e-10f);
        float inv = 1.0f / d;
        wk[k] = inv;
        wsum += inv;
    }
    const float rs = 1.0f / wsum;

    const float* F = flow1 + b * 3 * NPTS;
    float fx = 0.f, fy = 0.f, fz = 0.f;
#pragma unroll
    for (int k = 0; k < 3; k++) {
        int o = pp[k];
        float ww = wk[k] * rs;
        fx = fmaf(ww, F[o],            fx);
        fy = fmaf(ww, F[NPTS + o],     fy);
        fz = fmaf(ww, F[2 * NPTS + o], fz);
    }

    float* O = out + b * 3 * NPTS;
    O[n]            = qx - fx;
    O[NPTS + n]     = qy - fy;
    O[2 * NPTS + n] = qz - fz;
}

extern "C" void kernel_launch(void* const* d_in, const int* in_sizes, int n_in,
                              void* d_out, int out_size) {
    const float* xyz1  = (const float*)d_in[0];
    const float* xyz2  = (const float*)d_in[1];
    const float* flow1 = (const float*)d_in[2];
    float* out = (float*)d_out;

    k1_prep<<<(NB * (NPTS / 2) + 255) / 256, 256>>>(xyz1, flow1);
    k4_scan<<<(NQ / QPB) * SLICES, K4_THREADS>>>(xyz2);     // 1024 blocks
    k5_final<<<(NQ + 255) / 256, 256>>>(xyz2, flow1, out);
}

// round 5
// speedup vs baseline: 2.5191x; 1.0016x over previous
#include <cuda_runtime.h>
#include <math_constants.h>
#include <cstdint>

#define NB 2
#define NPTS 8192
#define NQ (NB * NPTS)
#define SLICES 16
#define SLICE_CAND (NPTS / SLICES)     // 512
#define SLICE_PAIRS (SLICE_CAND / 2)   // 256
#define QPB 256                        // queries per k4 block
#define K4_THREADS 128
#define TCH 4                          // tau sample chunks
#define CHPAIRS 256                    // pairs per chunk (512 candidates)
#define INF CUDART_INF_F
#define SENTINEL 0x7fffffff

// Candidate pair layout: pair j -> g_pairs[2j]=(x0,x1,y0,y1), g_pairs[2j+1]=(z0,z1,w0,w1)
__device__ float4 g_pairs[NB * (NPTS / 2) * 2];
__device__ float4 g_pts[NB * NPTS];                // (x,y,z,|p|^2) by original index
// Partials, transposed for coalescing: [slice][k(0..2)][query]
__device__ float  g_pScore[SLICES * 3 * NQ];
__device__ int    g_pIdx[SLICES * 3 * NQ];
// Tau pipeline
__device__ float  g_tc[TCH * 3 * NQ];              // per-chunk top-3 scores
__device__ float  g_tau[NQ];                       // nextafter(3rd-best of sample)

__device__ __forceinline__ uint64_t dup2(float v) {
    uint64_t r; asm("mov.b64 %0,{%1,%1};" : "=l"(r) : "f"(v)); return r;
}
__device__ __forceinline__ uint64_t fma2(uint64_t a, uint64_t b, uint64_t c) {
    uint64_t d; asm("fma.rn.f32x2 %0,%1,%2,%3;" : "=l"(d) : "l"(a), "l"(b), "l"(c)); return d;
}
__device__ __forceinline__ void unpack2(uint64_t v, float& lo, float& hi) {
    asm("mov.b64 {%0,%1},%2;" : "=f"(lo), "=f"(hi) : "l"(v));
}

#define INS3(bs0, bs1, bs2, bi0, bi1, bi2, s, id)            \
    if ((s) < (bs2)) {                                       \
        if ((s) < (bs1)) {                                   \
            bs2 = bs1; bi2 = bi1;                            \
            if ((s) < (bs0)) { bs1 = bs0; bi1 = bi0;         \
                               bs0 = (s); bi0 = (id); }      \
            else             { bs1 = (s); bi1 = (id); }      \
        } else { bs2 = (s); bi2 = (id); }                    \
    }

__global__ void k1_prep(const float* __restrict__ xyz1,
                        const float* __restrict__ flow1) {
    int t = blockIdx.x * blockDim.x + threadIdx.x;
    if (t >= NB * (NPTS / 2)) return;
    int b = t / (NPTS / 2), j = t % (NPTS / 2);
    const float* X = xyz1 + b * 3 * NPTS;
    const float* F = flow1 + b * 3 * NPTS;
    int c = 2 * j;
    float x0 = X[c] + F[c],                         x1 = X[c + 1] + F[c + 1];
    float y0 = X[NPTS + c] + F[NPTS + c],           y1 = X[NPTS + c + 1] + F[NPTS + c + 1];
    float z0 = X[2 * NPTS + c] + F[2 * NPTS + c],   z1 = X[2 * NPTS + c + 1] + F[2 * NPTS + c + 1];
    float w0 = fmaf(x0, x0, fmaf(y0, y0, z0 * z0));
    float w1 = fmaf(x1, x1, fmaf(y1, y1, z1 * z1));
    g_pairs[(b * (NPTS / 2) + j) * 2 + 0] = make_float4(x0, x1, y0, y1);
    g_pairs[(b * (NPTS / 2) + j) * 2 + 1] = make_float4(z0, z1, w0, w1);
    g_pts[b * NPTS + c]     = make_float4(x0, y0, z0, w0);
    g_pts[b * NPTS + c + 1] = make_float4(x1, y1, z1, w1);
}

// Per (query, chunk): branchless 3rd-best score over 512 sample candidates.
// Same fma2 chain as k4_scan so scores are bit-identical.
__global__ void __launch_bounds__(128)
k2_tau(const float* __restrict__ xyz2) {
    int idx = blockIdx.x * 128 + threadIdx.x;     // 0 .. 4*NQ-1
    int q   = idx & (NQ - 1);
    int ch  = idx >> 14;                          // 0..3
    int b = q >> 13, n = q & (NPTS - 1);
    const float* X2 = xyz2 + b * 3 * NPTS;
    const float qx = X2[n], qy = X2[NPTS + n], qz = X2[2 * NPTS + n];
    const uint64_t mx = dup2(-2.f * qx), my = dup2(-2.f * qy), mz = dup2(-2.f * qz);

    const ulonglong2* src = reinterpret_cast<const ulonglong2*>(
        g_pairs + (size_t)(b * (NPTS / 2) + ch * CHPAIRS) * 2);

    float b0 = INF, b1 = INF, b2 = INF;
#pragma unroll 4
    for (int j = 0; j < CHPAIRS; j++) {
        ulonglong2 v0 = src[2 * j];       // xp, yp
        ulonglong2 v1 = src[2 * j + 1];   // zp, wp
        float a0, a1;
        unpack2(fma2(v0.x, mx, fma2(v0.y, my, fma2(v1.x, mz, v1.y))), a0, a1);
        // merge sorted pair (lo<=hi) into sorted triple: keep 3 smallest of 5
        float lo = fminf(a0, a1), hi = fmaxf(a0, a1);
        float s1 = fmaxf(b0, lo);
        float s2 = fminf(b1, hi);
        float s3 = fmaxf(b1, hi);
        b0 = fminf(b0, lo);
        float r1 = fminf(s1, s2);
        b2 = fminf(fminf(b2, fmaxf(s1, s2)), s3);
        b1 = r1;
    }
    g_tc[(ch * 3 + 0) * NQ + q] = b0;
    g_tc[(ch * 3 + 1) * NQ + q] = b1;
    g_tc[(ch * 3 + 2) * NQ + q] = b2;
}

// Union-merge 4 chunk triples -> exact 3rd-best of the 2048 sample; bump one ulp.
__global__ void k3_tau2() {
    int q = blockIdx.x * blockDim.x + threadIdx.x;
    if (q >= NQ) return;
    float b0 = INF, b1 = INF, b2 = INF;
#pragma unroll
    for (int c = 0; c < TCH; c++)
#pragma unroll
        for (int k = 0; k < 3; k++) {
            float s = g_tc[(c * 3 + k) * NQ + q];
            if (s < b2) {
                if (s < b1) { b2 = b1; if (s < b0) { b1 = b0; b0 = s; } else b1 = s; }
                else b2 = s;
            }
        }
    g_tau[q] = nextafterf(b2, CUDART_INF_F);
}

// 256 queries/block vs one 512-candidate slice; trackers seeded with tau -> inserts rare.
__global__ void __launch_bounds__(K4_THREADS)
k4_scan(const float* __restrict__ xyz2) {
    __shared__ float4 sh[SLICE_PAIRS * 2];   // 8 KB

    const int blk   = blockIdx.x;
    const int slice = blk & (SLICES - 1);
    const int qg    = blk >> 4;              // 0..63
    const int batch = qg >> 5;               // 32 qgroups per batch
    const int qbase = (qg & 31) * QPB;
    const int lane  = threadIdx.x & 31;
    const int w     = threadIdx.x >> 5;

    const float4* src = g_pairs + (size_t)(batch * (NPTS / 2) + slice * SLICE_PAIRS) * 2;
#pragma unroll
    for (int i = threadIdx.x; i < SLICE_PAIRS * 2; i += K4_THREADS)
        sh[i] = src[i];
    __syncthreads();

    const int qA = qbase + w * 64 + lane;    // within batch
    const int qB = qA + 32;
    const int gqA = batch * NPTS + qA;
    const int gqB = batch * NPTS + qB;
    const float* X2 = xyz2 + batch * 3 * NPTS;
    const float aX = X2[qA], aY = X2[NPTS + qA], aZ = X2[2 * NPTS + qA];
    const float bX = X2[qB], bY = X2[NPTS + qB], bZ = X2[2 * NPTS + qB];

    const uint64_t Amx = dup2(-2.f * aX), Amy = dup2(-2.f * aY), Amz = dup2(-2.f * aZ);
    const uint64_t Bmx = dup2(-2.f * bX), Bmy = dup2(-2.f * bY), Bmz = dup2(-2.f * bZ);

    const float tA = g_tau[gqA];
    const float tB = g_tau[gqB];
    float As0 = tA, As1 = tA, As2 = tA;  int Ai0 = SENTINEL, Ai1 = SENTINEL, Ai2 = SENTINEL;
    float Bs0 = tB, Bs1 = tB, Bs2 = tB;  int Bi0 = SENTINEL, Bi1 = SENTINEL, Bi2 = SENTINEL;

    const uint32_t shbase = (uint32_t)__cvta_generic_to_shared(sh);
    const int cbase = slice * SLICE_CAND;

#pragma unroll 4
    for (int j = 0; j < SLICE_PAIRS; j += 2) {
        uint64_t xp0, yp0, zp0, wp0, xp1, yp1, zp1, wp1;
        const uint32_t addr = shbase + j * 32;
        asm("ld.shared.v2.u64 {%0,%1},[%2];"    : "=l"(xp0), "=l"(yp0) : "r"(addr));
        asm("ld.shared.v2.u64 {%0,%1},[%2+16];" : "=l"(zp0), "=l"(wp0) : "r"(addr));
        asm("ld.shared.v2.u64 {%0,%1},[%2+32];" : "=l"(xp1), "=l"(yp1) : "r"(addr));
        asm("ld.shared.v2.u64 {%0,%1},[%2+48];" : "=l"(zp1), "=l"(wp1) : "r"(addr));

        float a0, a1, a2, a3, b0, b1, b2, b3;
        unpack2(fma2(xp0, Amx, fma2(yp0, Amy, fma2(zp0, Amz, wp0))), a0, a1);
        unpack2(fma2(xp1, Amx, fma2(yp1, Amy, fma2(zp1, Amz, wp1))), a2, a3);
        unpack2(fma2(xp0, Bmx, fma2(yp0, Bmy, fma2(zp0, Bmz, wp0))), b0, b1);
        unpack2(fma2(xp1, Bmx, fma2(yp1, Bmy, fma2(zp1, Bmz, wp1))), b2, b3);

        if (fminf(fminf(a0, a1), fminf(a2, a3)) < As2) {
            const int id = cbase + 2 * j;
            INS3(As0, As1, As2, Ai0, Ai1, Ai2, a0, id);
            INS3(As0, As1, As2, Ai0, Ai1, Ai2, a1, id + 1);
            INS3(As0, As1, As2, Ai0, Ai1, Ai2, a2, id + 2);
            INS3(As0, As1, As2, Ai0, Ai1, Ai2, a3, id + 3);
        }
        if (fminf(fminf(b0, b1), fminf(b2, b3)) < Bs2) {
            const int id = cbase + 2 * j;
            INS3(Bs0, Bs1, Bs2, Bi0, Bi1, Bi2, b0, id);
            INS3(Bs0, Bs1, Bs2, Bi0, Bi1, Bi2, b1, id + 1);
            INS3(Bs0, Bs1, Bs2, Bi0, Bi1, Bi2, b2, id + 2);
            INS3(Bs0, Bs1, Bs2, Bi0, Bi1, Bi2, b3, id + 3);
        }
    }

    // Coalesced partial writes: [slice][k][query]
    const int sb = slice * 3 * NQ;
    g_pScore[sb + 0 * NQ + gqA] = As0;  g_pIdx[sb + 0 * NQ + gqA] = Ai0;
    g_pScore[sb + 1 * NQ + gqA] = As1;  g_pIdx[sb + 1 * NQ + gqA] = Ai1;
    g_pScore[sb + 2 * NQ + gqA] = As2;  g_pIdx[sb + 2 * NQ + gqA] = Ai2;
    g_pScore[sb + 0 * NQ + gqB] = Bs0;  g_pIdx[sb + 0 * NQ + gqB] = Bi0;
    g_pScore[sb + 1 * NQ + gqB] = Bs1;  g_pIdx[sb + 1 * NQ + gqB] = Bi1;
    g_pScore[sb + 2 * NQ + gqB] = Bs2;  g_pIdx[sb + 2 * NQ + gqB] = Bi2;
}

// Merge slice partials per query (sentinels lose: >=3 genuine entries score < tau+),
// then epilogue.
__global__ void k5_final(const float* __restrict__ xyz2,
                         const float* __restrict__ flow1,
                         float* __restrict__ out) {
    int q = blockIdx.x * blockDim.x + threadIdx.x;
    if (q >= NQ) return;
    const int b = q / NPTS, n = q % NPTS;

    float bs0 = INF, bs1 = INF, bs2 = INF;
    int   bi0 = 0,   bi1 = 0,   bi2 = 0;
#pragma unroll
    for (int sl = 0; sl < SLICES; sl++) {
#pragma unroll
        for (int k = 0; k < 3; k++) {
            float s = g_pScore[(sl * 3 + k) * NQ + q];
            int  id = g_pIdx[(sl * 3 + k) * NQ + q];
            INS3(bs0, bs1, bs2, bi0, bi1, bi2, s, id);
        }
    }

    const float* X2 = xyz2 + b * 3 * NPTS;
    const float qx = X2[n], qy = X2[NPTS + n], qz = X2[2 * NPTS + n];

    const float4* pts = g_pts + b * NPTS;
    int   pp[3] = { bi0, bi1, bi2 };
    float wk[3];
    float wsum = 0.f;
#pragma unroll
    for (int k = 0; k < 3; k++) {
        float4 p = pts[pp[k]];
        float dx = p.x - qx, dy = p.y - qy, dz = p.z - qz;
        float d = sqrtf(fmaf(dx, dx, fmaf(dy, dy, dz * dz)));
        d = fmaxf(d, 1e-10f);
        float inv = 1.0f / d;
        wk[k] = inv;
        wsum += inv;
    }
    const float rs = 1.0f / wsum;

    const float* F = flow1 + b * 3 * NPTS;
    float fx = 0.f, fy = 0.f, fz = 0.f;
#pragma unroll
    for (int k = 0; k < 3; k++) {
        int o = pp[k];
        float ww = wk[k] * rs;
        fx = fmaf(ww, F[o],            fx);
        fy = fmaf(ww, F[NPTS + o],     fy);
        fz = fmaf(ww, F[2 * NPTS + o], fz);
    }

    float* O = out + b * 3 * NPTS;
    O[n]            = qx - fx;
    O[NPTS + n]     = qy - fy;
    O[2 * NPTS + n] = qz - fz;
}

extern "C" void kernel_launch(void* const* d_in, const int* in_sizes, int n_in,
                              void* d_out, int out_size) {
    const float* xyz1  = (const float*)d_in[0];
    const float* xyz2  = (const float*)d_in[1];
    const float* flow1 = (const float*)d_in[2];
    float* out = (float*)d_out;

    k1_prep<<<(NB * (NPTS / 2) + 255) / 256, 256>>>(xyz1, flow1);
    k2_tau<<<(TCH * NQ) / 128, 128>>>(xyz2);               // 512 blocks
    k3_tau2<<<(NQ + 255) / 256, 256>>>();
    k4_scan<<<(NQ / QPB) * SLICES, K4_THREADS>>>(xyz2);    // 1024 blocks
    k5_final<<<(NQ + 255) / 256, 256>>>(xyz2, flow1, out);
}